// round 1
// baseline (speedup 1.0000x reference)
#include <cuda_runtime.h>
#include <cuda_bf16.h>
#include <cstdint>
#include <math.h>

// Problem constants (fixed by the dataset; runtime values cross-checked in kernel_launch)
#define BATCH 128
#define HID   1024
#define H2C   512
#define VOCAB 32000
#define TMAXX 64

// ---------------- device scratch (static allocation only) ----------------
__device__ float         g_state[2][BATCH * H2C];          // GRU hidden state per dir
__device__ float         g_gh[2][BATCH * 3 * H2C];         // gate pre-activations per dir
__device__ __nv_bfloat16 g_hcat[(size_t)TMAXX * BATCH * HID];      // [t*B+b][1024] bf16
__device__ __nv_bfloat16 g_wout[(size_t)VOCAB * HID];              // W_out in bf16

// ---------------- fp32 -> bf16 conversion ----------------
__global__ void f32_to_bf16_kernel(const float4* __restrict__ in,
                                   __nv_bfloat162* __restrict__ out, int n4) {
    int i = blockIdx.x * blockDim.x + threadIdx.x;
    if (i < n4) {
        float4 v = in[i];
        out[2 * i + 0] = __floats2bfloat162_rn(v.x, v.y);
        out[2 * i + 1] = __floats2bfloat162_rn(v.z, v.w);
    }
}

// ---------------- small fp32 GEMM:  C = (reluA?relu(A):A) @ B^T + bias ----------------
// BM=64, BN=64, BK=16, 256 threads, 4x4 microtile. blockIdx.z selects direction.
struct GemmF32Args {
    const float* A[2];
    const float* B[2];
    const float* bias[2];
    float*       C[2];
    int K;
    int N;
    int relu_a;
    float* Cdup;   // optional duplicate output (used by squeeze to init both dirs)
};

__global__ __launch_bounds__(256) void gemm_f32_nt(GemmF32Args args) {
    const int dir = blockIdx.z;
    const float* __restrict__ A    = args.A[dir];
    const float* __restrict__ Bm   = args.B[dir];
    const float* __restrict__ bias = args.bias[dir];
    float* __restrict__ C          = args.C[dir];
    const int K = args.K, N = args.N;

    __shared__ float As[16][68];
    __shared__ float Bs[16][68];

    const int tid = threadIdx.x;
    const int tx = tid & 15, ty = tid >> 4;
    const int m0 = blockIdx.y * 64, n0 = blockIdx.x * 64;
    const int lrow = tid >> 2;            // 0..63
    const int lk   = (tid & 3) * 4;       // 0,4,8,12

    float acc[4][4] = {};

    for (int k0 = 0; k0 < K; k0 += 16) {
        float4 av = *(const float4*)(A + (size_t)(m0 + lrow) * K + k0 + lk);
        if (args.relu_a) {
            av.x = fmaxf(av.x, 0.f); av.y = fmaxf(av.y, 0.f);
            av.z = fmaxf(av.z, 0.f); av.w = fmaxf(av.w, 0.f);
        }
        float4 bv = *(const float4*)(Bm + (size_t)(n0 + lrow) * K + k0 + lk);
        As[lk + 0][lrow] = av.x; As[lk + 1][lrow] = av.y;
        As[lk + 2][lrow] = av.z; As[lk + 3][lrow] = av.w;
        Bs[lk + 0][lrow] = bv.x; Bs[lk + 1][lrow] = bv.y;
        Bs[lk + 2][lrow] = bv.z; Bs[lk + 3][lrow] = bv.w;
        __syncthreads();

#pragma unroll
        for (int k = 0; k < 16; k++) {
            float4 a4 = *(const float4*)&As[k][ty * 4];
            float4 b4 = *(const float4*)&Bs[k][tx * 4];
            float a[4] = {a4.x, a4.y, a4.z, a4.w};
            float b[4] = {b4.x, b4.y, b4.z, b4.w};
#pragma unroll
            for (int i = 0; i < 4; i++)
#pragma unroll
                for (int j = 0; j < 4; j++)
                    acc[i][j] += a[i] * b[j];
        }
        __syncthreads();
    }

#pragma unroll
    for (int i = 0; i < 4; i++)
#pragma unroll
        for (int j = 0; j < 4; j++) {
            int m = m0 + ty * 4 + i;
            int n = n0 + tx * 4 + j;
            float v = acc[i][j] + (bias ? bias[n] : 0.f);
            C[(size_t)m * N + n] = v;
            if (args.Cdup) args.Cdup[(size_t)m * N + n] = v;
        }
}

// ---------------- GRU gate elementwise step ----------------
__global__ void gru_gate_kernel(const float* __restrict__ bih_f,
                                const float* __restrict__ bih_r,
                                int t, int T) {
    const int dir = blockIdx.y;
    const int i = blockIdx.x * blockDim.x + threadIdx.x;   // < BATCH*H2C
    const int b = i >> 9;         // /512
    const int j = i & (H2C - 1);  // %512
    const float* __restrict__ gh  = g_gh[dir];
    float* __restrict__ st        = g_state[dir];
    const float* __restrict__ bih = dir ? bih_r : bih_f;

    float ghr = gh[b * 3 * H2C + j];
    float ghz = gh[b * 3 * H2C + H2C + j];
    float ghn = gh[b * 3 * H2C + 2 * H2C + j];
    float r = 1.f / (1.f + expf(-(bih[j] + ghr)));
    float z = 1.f / (1.f + expf(-(bih[H2C + j] + ghz)));
    float n = tanhf(bih[2 * H2C + j] + r * ghn);
    float h = st[b * H2C + j];
    float hn = (1.f - z) * n + z * h;
    st[b * H2C + j] = hn;

    int tt = dir ? (T - 1 - t) : t;
    g_hcat[((size_t)tt * BATCH + b) * HID + dir * H2C + j] = __float2bfloat16(hn);
}

// ---------------- big bf16 GEMM: C[M,N] = A[M,K] @ B[N,K]^T + bias ----------------
// BM=BN=128, BK=32, 256 threads = 8 warps (2m x 4n), warp tile 64x32, mma m16n8k16.

__device__ __forceinline__ int sw_off(int row, int k) {
    // row stride 32 bf16 (64B); 16B chunks xor-swizzled by (row>>1)&3
    return row * 32 + ((((k >> 3) ^ ((row >> 1) & 3)) & 3) << 3) + (k & 7);
}

__device__ __forceinline__ void cp_async16(uint32_t smem, const void* g) {
    asm volatile("cp.async.cg.shared.global [%0], [%1], 16;\n" :: "r"(smem), "l"(g));
}
__device__ __forceinline__ void cp_commit() {
    asm volatile("cp.async.commit_group;\n" ::: "memory");
}

__device__ __forceinline__ void ldm4(uint32_t& a, uint32_t& b, uint32_t& c, uint32_t& d,
                                     uint32_t addr) {
    asm volatile("ldmatrix.sync.aligned.m8n8.x4.shared.b16 {%0,%1,%2,%3}, [%4];"
                 : "=r"(a), "=r"(b), "=r"(c), "=r"(d) : "r"(addr));
}

__device__ __forceinline__ void mma_bf16(float* c, const uint32_t* a, const uint32_t* b) {
    asm volatile(
        "mma.sync.aligned.m16n8k16.row.col.f32.bf16.bf16.f32 "
        "{%0,%1,%2,%3}, {%4,%5,%6,%7}, {%8,%9}, {%0,%1,%2,%3};"
        : "+f"(c[0]), "+f"(c[1]), "+f"(c[2]), "+f"(c[3])
        : "r"(a[0]), "r"(a[1]), "r"(a[2]), "r"(a[3]), "r"(b[0]), "r"(b[1]));
}

__global__ __launch_bounds__(256) void gemm_big_bf16(
    const __nv_bfloat16* __restrict__ Ag, const __nv_bfloat16* __restrict__ Bg,
    const float* __restrict__ bias, float* __restrict__ Cg,
    int M, int N, int K) {
    __shared__ __align__(16) __nv_bfloat16 As[2][128 * 32];
    __shared__ __align__(16) __nv_bfloat16 Bs[2][128 * 32];

    const int tid = threadIdx.x;
    const int warp = tid >> 5, lane = tid & 31;
    const int wm = warp >> 2, wn = warp & 3;
    const int m0 = blockIdx.y * 128, n0 = blockIdx.x * 128;

    // cp.async layout: idx in [0,512): row = idx>>2, chunk = idx&3 (each 8 bf16 = 16B)
    const int r0 = tid >> 2, c0 = tid & 3;
    const uint32_t saA = (uint32_t)__cvta_generic_to_shared(&As[0][0]);
    const uint32_t saB = (uint32_t)__cvta_generic_to_shared(&Bs[0][0]);
    const uint32_t offLo = (uint32_t)sw_off(r0, c0 * 8) * 2;
    const uint32_t offHi = (uint32_t)sw_off(r0 + 64, c0 * 8) * 2;

    const __nv_bfloat16* Arow0 = Ag + (size_t)(m0 + r0) * K + c0 * 8;
    const __nv_bfloat16* Arow1 = Ag + (size_t)(m0 + r0 + 64) * K + c0 * 8;
    const __nv_bfloat16* Brow0 = Bg + (size_t)(n0 + r0) * K + c0 * 8;
    const __nv_bfloat16* Brow1 = Bg + (size_t)(n0 + r0 + 64) * K + c0 * 8;

    float acc[4][4][4] = {};

    const int NK = K / 32;

    auto load_stage = [&](int kt, int s) {
        const uint32_t bo = (uint32_t)(s * 128 * 32 * 2);
        cp_async16(saA + bo + offLo, Arow0 + kt * 32);
        cp_async16(saA + bo + offHi, Arow1 + kt * 32);
        cp_async16(saB + bo + offLo, Brow0 + kt * 32);
        cp_async16(saB + bo + offHi, Brow1 + kt * 32);
        cp_commit();
    };

    load_stage(0, 0);

    for (int kt = 0; kt < NK; kt++) {
        const int s = kt & 1;
        if (kt + 1 < NK) {
            load_stage(kt + 1, s ^ 1);
            asm volatile("cp.async.wait_group 1;\n" ::: "memory");
        } else {
            asm volatile("cp.async.wait_group 0;\n" ::: "memory");
        }
        __syncthreads();

        const uint32_t baseA = saA + (uint32_t)(s * 128 * 32 * 2);
        const uint32_t baseB = saB + (uint32_t)(s * 128 * 32 * 2);

#pragma unroll
        for (int ks = 0; ks < 32; ks += 16) {
            uint32_t afr[4][4];
#pragma unroll
            for (int mi = 0; mi < 4; mi++) {
                int row = wm * 64 + mi * 16 + (lane & 15);
                int kk = ks + ((lane >> 4) << 3);
                ldm4(afr[mi][0], afr[mi][1], afr[mi][2], afr[mi][3],
                     baseA + (uint32_t)sw_off(row, kk) * 2);
            }
            uint32_t bfr[4][2];
#pragma unroll
            for (int ni = 0; ni < 2; ni++) {
                int row = wn * 32 + ni * 16 + ((lane >> 4) << 3) + (lane & 7);
                int kk = ks + (((lane >> 3) & 1) << 3);
                uint32_t q0, q1, q2, q3;
                ldm4(q0, q1, q2, q3, baseB + (uint32_t)sw_off(row, kk) * 2);
                bfr[ni * 2 + 0][0] = q0; bfr[ni * 2 + 0][1] = q1;
                bfr[ni * 2 + 1][0] = q2; bfr[ni * 2 + 1][1] = q3;
            }
#pragma unroll
            for (int mi = 0; mi < 4; mi++)
#pragma unroll
                for (int nf = 0; nf < 4; nf++)
                    mma_bf16(acc[mi][nf], afr[mi], bfr[nf]);
        }
        __syncthreads();
    }

    // epilogue: add bias, fp32 store
#pragma unroll
    for (int mi = 0; mi < 4; mi++) {
#pragma unroll
        for (int nf = 0; nf < 4; nf++) {
            int row = m0 + wm * 64 + mi * 16 + (lane >> 2);
            int col = n0 + wn * 32 + nf * 8 + (lane & 3) * 2;
            float b0 = bias[col], b1 = bias[col + 1];
            float2 v0 = make_float2(acc[mi][nf][0] + b0, acc[mi][nf][1] + b1);
            float2 v1 = make_float2(acc[mi][nf][2] + b0, acc[mi][nf][3] + b1);
            *(float2*)&Cg[(size_t)row * N + col] = v0;
            *(float2*)&Cg[(size_t)(row + 8) * N + col] = v1;
        }
    }
}

// ---------------- in-place log_softmax over rows of length V ----------------
__device__ float block_reduce(float v, float* red, bool is_max) {
    __syncthreads();   // protect red[] reuse across successive calls
#pragma unroll
    for (int o = 16; o; o >>= 1) {
        float w = __shfl_xor_sync(0xffffffff, v, o);
        v = is_max ? fmaxf(v, w) : (v + w);
    }
    if ((threadIdx.x & 31) == 0) red[threadIdx.x >> 5] = v;
    __syncthreads();
    if (threadIdx.x < 32) {
        float w = (threadIdx.x < (blockDim.x >> 5)) ? red[threadIdx.x]
                                                    : (is_max ? -INFINITY : 0.f);
#pragma unroll
        for (int o = 16; o; o >>= 1) {
            float u = __shfl_xor_sync(0xffffffff, w, o);
            w = is_max ? fmaxf(w, u) : (w + u);
        }
        if (threadIdx.x == 0) red[0] = w;
    }
    __syncthreads();
    return red[0];
}

__global__ void logsoftmax_kernel(float* __restrict__ out, int V) {
    extern __shared__ float row[];
    __shared__ float red[32];
    float* x = out + (size_t)blockIdx.x * V;
    const int tid = threadIdx.x;

    float mx = -INFINITY;
    for (int i = tid * 4; i < V; i += blockDim.x * 4) {
        float4 v = *(const float4*)(x + i);
        *(float4*)(row + i) = v;
        mx = fmaxf(mx, fmaxf(fmaxf(v.x, v.y), fmaxf(v.z, v.w)));
    }
    mx = block_reduce(mx, red, true);

    float s = 0.f;
    for (int i = tid * 4; i < V; i += blockDim.x * 4) {
        float4 v = *(const float4*)(row + i);
        s += expf(v.x - mx) + expf(v.y - mx) + expf(v.z - mx) + expf(v.w - mx);
    }
    s = block_reduce(s, red, false);
    const float lse = mx + logf(s);

    for (int i = tid * 4; i < V; i += blockDim.x * 4) {
        float4 v = *(const float4*)(row + i);
        v.x -= lse; v.y -= lse; v.z -= lse; v.w -= lse;
        *(float4*)(x + i) = v;
    }
}

// ---------------- launcher ----------------
extern "C" void kernel_launch(void* const* d_in, const int* in_sizes, int n_in,
                              void* d_out, int out_size) {
    const float* hidden = (const float*)d_in[0];
    const float* W_sq   = (const float*)d_in[1];
    const float* b_sq   = (const float*)d_in[2];
    const float* W_hh_f = (const float*)d_in[3];
    const float* b_ih_f = (const float*)d_in[4];
    const float* b_hh_f = (const float*)d_in[5];
    const float* W_hh_r = (const float*)d_in[6];
    const float* b_ih_r = (const float*)d_in[7];
    const float* b_hh_r = (const float*)d_in[8];
    const float* W_out  = (const float*)d_in[9];
    const float* b_out  = (const float*)d_in[10];
    float* out = (float*)d_out;

    const int h2 = in_sizes[2];              // 512
    const int Hh = 2 * h2;                   // 1024
    const int Bb = in_sizes[0] / Hh;         // 128
    const int V  = in_sizes[10];             // 32000
    const int T  = out_size / (Bb * V);      // 32
    if (T > TMAXX) return;

    float *state0, *gh0;
    __nv_bfloat16 *hcat, *wout;
    cudaGetSymbolAddress((void**)&state0, g_state);
    cudaGetSymbolAddress((void**)&gh0, g_gh);
    cudaGetSymbolAddress((void**)&hcat, g_hcat);
    cudaGetSymbolAddress((void**)&wout, g_wout);
    float* state1 = state0 + BATCH * H2C;

    // 1. W_out -> bf16
    {
        int n4 = V * Hh / 4;
        f32_to_bf16_kernel<<<(n4 + 255) / 256, 256>>>(
            (const float4*)W_out, (__nv_bfloat162*)wout, n4);
    }

    // 2. squeeze: enc = relu(hidden) @ W_sq^T + b_sq   -> both direction states
    {
        GemmF32Args a = {};
        a.A[0] = hidden; a.B[0] = W_sq; a.bias[0] = b_sq; a.C[0] = state0;
        a.K = Hh; a.N = h2; a.relu_a = 1; a.Cdup = state1;
        gemm_f32_nt<<<dim3(h2 / 64, Bb / 64, 1), 256>>>(a);
    }

    // 3. GRU recurrence, both directions per launch
    {
        GemmF32Args a = {};
        a.A[0] = state0; a.A[1] = state1;
        a.B[0] = W_hh_f; a.B[1] = W_hh_r;
        a.bias[0] = b_hh_f; a.bias[1] = b_hh_r;
        a.C[0] = gh0; a.C[1] = gh0 + BATCH * 3 * H2C;
        a.K = h2; a.N = 3 * h2; a.relu_a = 0; a.Cdup = nullptr;
        for (int t = 0; t < T; t++) {
            gemm_f32_nt<<<dim3(3 * h2 / 64, Bb / 64, 2), 256>>>(a);
            gru_gate_kernel<<<dim3(Bb * h2 / 256, 2), 256>>>(b_ih_f, b_ih_r, t, T);
        }
    }

    // 4. logits = hcat @ W_out^T + b_out  (bf16 tensor cores, fp32 accum)
    gemm_big_bf16<<<dim3(V / 128, (T * Bb) / 128), 256>>>(
        hcat, wout, b_out, out, T * Bb, V, Hh);

    // 5. in-place log_softmax per row
    cudaFuncSetAttribute(logsoftmax_kernel,
                         cudaFuncAttributeMaxDynamicSharedMemorySize,
                         V * (int)sizeof(float));
    logsoftmax_kernel<<<T * Bb, 1024, V * sizeof(float)>>>(out, V);
}